// round 2
// baseline (speedup 1.0000x reference)
#include <cuda_runtime.h>
#include <cuda_bf16.h>

// Problem constants (from reference): N=2,000,000 voxels, CIN=16, COUT=32, K2=9.
#define MAXN 2000000
#define CIN 16
#define COUT 32
#define K2 9

// Scratch for the intermediate h1 = relu(conv1(x)) : [N, 32] fp32 = 256 MB.
__device__ float g_h1[(size_t)MAXN * COUT];

// ---------- packed f32x2 helpers (ptxas won't auto-fuse FFMA2 from C++) ----------
__device__ __forceinline__ unsigned long long pack2(float a, float b) {
    unsigned long long r;
    asm("mov.b64 %0, {%1, %2};" : "=l"(r) : "f"(a), "f"(b));
    return r;
}
__device__ __forceinline__ float2 unpack2(unsigned long long v) {
    float2 f;
    asm("mov.b64 {%0, %1}, %2;" : "=f"(f.x), "=f"(f.y) : "l"(v));
    return f;
}
__device__ __forceinline__ unsigned long long fma2(unsigned long long a,
                                                   unsigned long long b,
                                                   unsigned long long c) {
    unsigned long long d;
    asm("fma.rn.f32x2 %0, %1, %2, %3;" : "=l"(d) : "l"(a), "l"(b), "l"(c));
    return d;
}

// =====================================================================
// Kernel 1: h1 = relu( sum_k mask[k]*x[idx[k]] @ W1[k] + b1 )
// one thread per voxel; 16 f32x2 accumulators (= 32 couts)
// =====================================================================
__global__ __launch_bounds__(256)
void conv1_relu_kernel(const float* __restrict__ x,
                       const float* __restrict__ W1,
                       const float* __restrict__ b1,
                       const int* __restrict__ nbr_idx,
                       const unsigned int* __restrict__ nbr_mask,  // bool stored 4-byte: nonzero == true
                       int n) {
    __shared__ unsigned long long Ws[K2 * CIN * (COUT / 2)];   // 18 KB
    __shared__ float bs[COUT];

    for (int t = threadIdx.x; t < K2 * CIN * (COUT / 2); t += blockDim.x) {
        int row = t >> 4;          // (k, cin)
        int p   = t & 15;          // cout pair
        Ws[t] = pack2(W1[row * COUT + 2 * p], W1[row * COUT + 2 * p + 1]);
    }
    if (threadIdx.x < COUT) bs[threadIdx.x] = b1[threadIdx.x];
    __syncthreads();

    int i = blockIdx.x * blockDim.x + threadIdx.x;
    if (i >= n) return;

    unsigned long long acc[COUT / 2];
#pragma unroll
    for (int o = 0; o < COUT / 2; o++) acc[o] = pack2(bs[2 * o], bs[2 * o + 1]);

    for (int k = 0; k < K2; k++) {
        size_t off = (size_t)k * n + i;
        if (nbr_mask[off] == 0u) continue;
        int idx = nbr_idx[off];
        const float4* xr = (const float4*)(x + (size_t)idx * CIN);
        float4 r0 = xr[0], r1 = xr[1], r2 = xr[2], r3 = xr[3];
        float v[CIN] = {r0.x, r0.y, r0.z, r0.w, r1.x, r1.y, r1.z, r1.w,
                        r2.x, r2.y, r2.z, r2.w, r3.x, r3.y, r3.z, r3.w};
        const unsigned long long* wk = Ws + k * (CIN * (COUT / 2));
#pragma unroll
        for (int c = 0; c < CIN; c++) {
            unsigned long long vv = pack2(v[c], v[c]);
#pragma unroll
            for (int o = 0; o < COUT / 2; o++)
                acc[o] = fma2(vv, wk[c * (COUT / 2) + o], acc[o]);
        }
    }

    float2* hout = (float2*)(g_h1 + (size_t)i * COUT);
#pragma unroll
    for (int o = 0; o < COUT / 2; o++) {
        float2 f = unpack2(acc[o]);
        hout[o] = make_float2(fmaxf(f.x, 0.0f), fmaxf(f.y, 0.0f));
    }
}

// =====================================================================
// Kernel 2: out = relu( sum_k mask[k]*h1[idx[k]] @ W2[k] + b2 + x @ Wp + bp )
// =====================================================================
__global__ __launch_bounds__(256)
void conv2_resid_kernel(const float* __restrict__ x,
                        const float* __restrict__ W2,
                        const float* __restrict__ b2,
                        const float* __restrict__ Wp,
                        const float* __restrict__ bp,
                        const int* __restrict__ nbr_idx,
                        const unsigned int* __restrict__ nbr_mask,
                        float* __restrict__ out,
                        int n) {
    __shared__ unsigned long long Ws2[K2 * COUT * (COUT / 2)];  // 36 KB
    __shared__ unsigned long long Wps[CIN * (COUT / 2)];        // 2 KB
    __shared__ unsigned long long bsum[COUT / 2];

    for (int t = threadIdx.x; t < K2 * COUT * (COUT / 2); t += blockDim.x) {
        int row = t >> 4;
        int p   = t & 15;
        Ws2[t] = pack2(W2[row * COUT + 2 * p], W2[row * COUT + 2 * p + 1]);
    }
    for (int t = threadIdx.x; t < CIN * (COUT / 2); t += blockDim.x) {
        int row = t >> 4;
        int p   = t & 15;
        Wps[t] = pack2(Wp[row * COUT + 2 * p], Wp[row * COUT + 2 * p + 1]);
    }
    if (threadIdx.x < COUT / 2) {
        int o = threadIdx.x;
        bsum[o] = pack2(b2[2 * o] + bp[2 * o], b2[2 * o + 1] + bp[2 * o + 1]);
    }
    __syncthreads();

    int i = blockIdx.x * blockDim.x + threadIdx.x;
    if (i >= n) return;

    unsigned long long acc[COUT / 2];
#pragma unroll
    for (int o = 0; o < COUT / 2; o++) acc[o] = bsum[o];

    // 1x1 residual projection from x (coalesced per-thread row)
    {
        const float4* xr = (const float4*)(x + (size_t)i * CIN);
        float4 r0 = xr[0], r1 = xr[1], r2 = xr[2], r3 = xr[3];
        float v[CIN] = {r0.x, r0.y, r0.z, r0.w, r1.x, r1.y, r1.z, r1.w,
                        r2.x, r2.y, r2.z, r2.w, r3.x, r3.y, r3.z, r3.w};
#pragma unroll
        for (int c = 0; c < CIN; c++) {
            unsigned long long vv = pack2(v[c], v[c]);
#pragma unroll
            for (int o = 0; o < COUT / 2; o++)
                acc[o] = fma2(vv, Wps[c * (COUT / 2) + o], acc[o]);
        }
    }

    // 3x3 sparse conv over h1 (random 128B-row gathers)
    for (int k = 0; k < K2; k++) {
        size_t off = (size_t)k * n + i;
        if (nbr_mask[off] == 0u) continue;
        int idx = nbr_idx[off];
        const float4* hr = (const float4*)(g_h1 + (size_t)idx * COUT);
        float h[COUT];
#pragma unroll
        for (int q = 0; q < COUT / 4; q++) {
            float4 r = hr[q];
            h[4 * q] = r.x; h[4 * q + 1] = r.y; h[4 * q + 2] = r.z; h[4 * q + 3] = r.w;
        }
        const unsigned long long* wk = Ws2 + k * (COUT * (COUT / 2));
#pragma unroll
        for (int c = 0; c < COUT; c++) {
            unsigned long long vv = pack2(h[c], h[c]);
#pragma unroll
            for (int o = 0; o < COUT / 2; o++)
                acc[o] = fma2(vv, wk[c * (COUT / 2) + o], acc[o]);
        }
    }

    float2* op = (float2*)(out + (size_t)i * COUT);
#pragma unroll
    for (int o = 0; o < COUT / 2; o++) {
        float2 f = unpack2(acc[o]);
        op[o] = make_float2(fmaxf(f.x, 0.0f), fmaxf(f.y, 0.0f));
    }
}

// =====================================================================
// Launch.  Input order: x, W1, b1, W2, b2, Wp, bp, nbr_idx, nbr_mask
// =====================================================================
extern "C" void kernel_launch(void* const* d_in, const int* in_sizes, int n_in,
                              void* d_out, int out_size) {
    const float* x  = (const float*)d_in[0];
    const float* W1 = (const float*)d_in[1];
    const float* b1 = (const float*)d_in[2];
    const float* W2 = (const float*)d_in[3];
    const float* b2 = (const float*)d_in[4];
    const float* Wp = (const float*)d_in[5];
    const float* bp = (const float*)d_in[6];
    const int* nbr_idx = (const int*)d_in[7];
    const unsigned int* nbr_mask = (const unsigned int*)d_in[8];
    float* out = (float*)d_out;

    int n = in_sizes[0] / CIN;
    if (n > MAXN) n = MAXN;

    const int threads = 256;
    const int blocks = (n + threads - 1) / threads;

    conv1_relu_kernel<<<blocks, threads>>>(x, W1, b1, nbr_idx, nbr_mask, n);
    conv2_resid_kernel<<<blocks, threads>>>(x, W2, b2, Wp, bp, nbr_idx, nbr_mask, out, n);
}